// round 1
// baseline (speedup 1.0000x reference)
#include <cuda_runtime.h>
#include <math_constants.h>

// Problem shape (fixed by the benchmark)
#define BB   16
#define KC   5
#define NP   4096
#define DD   1024
#define KNN  9

#define BLOCKS_PER_B 32        // sims kernel: blocks per batch
#define RPG          4         // rows per warp group in sims kernel

// -------- scratch (no device allocation allowed -> __device__ globals) ------
__device__ float g_cue_n[BB * KC * DD];     // normalized cue (327 KB)
__device__ float g_sims[BB * KC * NP];      // cosine sims    (1.3 MB)
__device__ float g_invnorm[BB * NP];        // 1/||patch||    (256 KB)

// -------- packed f32x2 helpers (Blackwell FFMA2; halves FFMA issue) ---------
__device__ __forceinline__ void fma2(unsigned long long& d,
                                     unsigned long long a,
                                     unsigned long long b) {
    asm("fma.rn.f32x2 %0, %1, %2, %0;" : "+l"(d) : "l"(a), "l"(b));
}
__device__ __forceinline__ float sum2(unsigned long long p) {
    return __uint_as_float((unsigned int)(p & 0xffffffffu)) +
           __uint_as_float((unsigned int)(p >> 32));
}

// ============================================================================
// Kernel 0: L2-normalize cue rows. grid = B*K blocks, 256 threads.
// ============================================================================
__global__ void __launch_bounds__(256) normalize_cue_kernel(const float* __restrict__ cue) {
    const int bk = blockIdx.x;                 // 0..79
    const float* row = cue + (size_t)bk * DD;
    const int warp = threadIdx.x >> 5, lane = threadIdx.x & 31;

    float ss = 0.f;
    for (int i = threadIdx.x; i < DD; i += 256) {
        float v = row[i];
        ss += v * v;
    }
    __shared__ float s_red[8];
    #pragma unroll
    for (int o = 16; o; o >>= 1) ss += __shfl_xor_sync(0xffffffffu, ss, o);
    if (lane == 0) s_red[warp] = ss;
    __syncthreads();
    if (warp == 0) {
        float v = (lane < 8) ? s_red[lane] : 0.f;
        #pragma unroll
        for (int o = 4; o; o >>= 1) v += __shfl_xor_sync(0xffffffffu, v, o);
        if (lane == 0) s_red[0] = 1.0f / fmaxf(sqrtf(v), 1e-12f);
    }
    __syncthreads();
    const float inv = s_red[0];
    for (int i = threadIdx.x; i < DD; i += 256)
        g_cue_n[(size_t)bk * DD + i] = row[i] * inv;
}

// ============================================================================
// Kernel 1: one pass over patches. Each warp: 4 rows; per row compute
// dot with 5 normalized cues + self-dot. Writes sims (already divided by
// patch norm) and invnorm. Memory-bound: 268 MB streamed once.
// ============================================================================
__global__ void __launch_bounds__(256, 3) sims_kernel(const float* __restrict__ patches) {
    const int b = blockIdx.y;

    __shared__ ulonglong2 s_cue[KC * DD / 4];   // 5 x 1024 floats = 20 KB
    {
        const ulonglong2* src =
            (const ulonglong2*)(g_cue_n + (size_t)b * KC * DD);
        for (int i = threadIdx.x; i < KC * DD / 4; i += 256) s_cue[i] = src[i];
    }
    __syncthreads();

    const int warp = threadIdx.x >> 5;
    const int lane = threadIdx.x & 31;
    const int rows_per_block = NP / BLOCKS_PER_B;          // 128
    const int row0 = blockIdx.x * rows_per_block;

    for (int g = warp * RPG; g < rows_per_block; g += 8 * RPG) {
        const int r = row0 + g;
        const ulonglong2* p =
            (const ulonglong2*)(patches + ((size_t)b * NP + r) * DD);

        unsigned long long acc[RPG][6];
        #pragma unroll
        for (int rr = 0; rr < RPG; rr++)
            #pragma unroll
            for (int i = 0; i < 6; i++) acc[rr][i] = 0ull;   // two packed zeros

        #pragma unroll
        for (int j = 0; j < 8; j++) {
            const int off = lane + j * 32;                   // 256 ull2 per row
            ulonglong2 v[RPG];
            #pragma unroll
            for (int rr = 0; rr < RPG; rr++) v[rr] = p[off + rr * (DD / 4)];

            #pragma unroll
            for (int rr = 0; rr < RPG; rr++) {
                fma2(acc[rr][5], v[rr].x, v[rr].x);
                fma2(acc[rr][5], v[rr].y, v[rr].y);
            }
            #pragma unroll
            for (int k = 0; k < KC; k++) {
                const ulonglong2 c = s_cue[k * (DD / 4) + off];
                #pragma unroll
                for (int rr = 0; rr < RPG; rr++) {
                    fma2(acc[rr][k], v[rr].x, c.x);
                    fma2(acc[rr][k], v[rr].y, c.y);
                }
            }
        }

        #pragma unroll
        for (int rr = 0; rr < RPG; rr++) {
            float s[6];
            #pragma unroll
            for (int i = 0; i < 6; i++) s[i] = sum2(acc[rr][i]);
            #pragma unroll
            for (int i = 0; i < 6; i++)
                #pragma unroll
                for (int o = 16; o; o >>= 1)
                    s[i] += __shfl_xor_sync(0xffffffffu, s[i], o);
            if (lane == 0) {
                const float inv = 1.0f / fmaxf(sqrtf(s[5]), 1e-12f);
                g_invnorm[(size_t)b * NP + r + rr] = inv;
                #pragma unroll
                for (int k = 0; k < KC; k++)
                    g_sims[((size_t)b * KC + k) * NP + r + rr] = s[k] * inv;
            }
        }
    }
}

// ============================================================================
// Kernel 2: per (b,k): top-9 over N=4096 sims, then mean of the 9 normalized
// patch rows. grid = 80 blocks, 256 threads. Gather = 2.9 MB total.
// ============================================================================
__global__ void __launch_bounds__(256) topk_kernel(const float* __restrict__ patches,
                                                   float* __restrict__ out) {
    const int bk = blockIdx.x;          // 0..79
    const int b = bk / KC;

    __shared__ float s_sims[NP];        // 16 KB
    __shared__ float s_rv[8];
    __shared__ int   s_ri[8];
    __shared__ int   s_top[KNN];
    __shared__ float s_inv[KNN];

    const float* simrow = g_sims + (size_t)bk * NP;
    for (int i = threadIdx.x; i < NP; i += 256) s_sims[i] = simrow[i];
    __syncthreads();

    const int warp = threadIdx.x >> 5, lane = threadIdx.x & 31;

    for (int it = 0; it < KNN; it++) {
        float bv = -CUDART_INF_F;
        int bi = NP;
        for (int i = threadIdx.x; i < NP; i += 256) {
            float v = s_sims[i];
            if (v > bv) { bv = v; bi = i; }     // ascending i keeps lowest index on tie
        }
        #pragma unroll
        for (int o = 16; o; o >>= 1) {
            float ov = __shfl_xor_sync(0xffffffffu, bv, o);
            int   oi = __shfl_xor_sync(0xffffffffu, bi, o);
            if (ov > bv || (ov == bv && oi < bi)) { bv = ov; bi = oi; }
        }
        if (lane == 0) { s_rv[warp] = bv; s_ri[warp] = bi; }
        __syncthreads();
        if (warp == 0) {
            bv = (lane < 8) ? s_rv[lane] : -CUDART_INF_F;
            bi = (lane < 8) ? s_ri[lane] : NP;
            #pragma unroll
            for (int o = 4; o; o >>= 1) {
                float ov = __shfl_xor_sync(0xffffffffu, bv, o);
                int   oi = __shfl_xor_sync(0xffffffffu, bi, o);
                if (ov > bv || (ov == bv && oi < bi)) { bv = ov; bi = oi; }
            }
            if (lane == 0) {
                s_top[it] = bi;
                s_sims[bi] = -CUDART_INF_F;     // mask for next iteration
            }
        }
        __syncthreads();
    }

    if (threadIdx.x < KNN)
        s_inv[threadIdx.x] = g_invnorm[(size_t)b * NP + s_top[threadIdx.x]];
    __syncthreads();

    // each thread owns one float4 of the D=1024 output
    float4 acc = make_float4(0.f, 0.f, 0.f, 0.f);
    #pragma unroll
    for (int i = 0; i < KNN; i++) {
        const float4* prow =
            (const float4*)(patches + ((size_t)b * NP + s_top[i]) * DD);
        const float4 v = prow[threadIdx.x];
        const float inv = s_inv[i];
        acc.x += v.x * inv;
        acc.y += v.y * inv;
        acc.z += v.z * inv;
        acc.w += v.w * inv;
    }
    const float sc = 1.0f / (float)KNN;
    float4 o4 = make_float4(acc.x * sc, acc.y * sc, acc.z * sc, acc.w * sc);
    ((float4*)out)[(size_t)bk * (DD / 4) + threadIdx.x] = o4;
}

// ============================================================================
extern "C" void kernel_launch(void* const* d_in, const int* in_sizes, int n_in,
                              void* d_out, int out_size) {
    const float* cue     = (const float*)d_in[0];
    const float* patches = (const float*)d_in[1];
    // defensive: identify by element count (cue = 81920, patches = 67108864)
    if (n_in >= 2 && in_sizes[0] > in_sizes[1]) {
        cue     = (const float*)d_in[1];
        patches = (const float*)d_in[0];
    }

    normalize_cue_kernel<<<BB * KC, 256>>>(cue);

    dim3 g1(BLOCKS_PER_B, BB);
    sims_kernel<<<g1, 256>>>(patches);

    topk_kernel<<<BB * KC, 256>>>(patches, (float*)d_out);
}

// round 2
// speedup vs baseline: 2.8500x; 2.8500x over previous
#include <cuda_runtime.h>
#include <math_constants.h>

// Problem shape (fixed by the benchmark)
#define BB   16
#define KC   5
#define NP   4096
#define DD   1024
#define KNN  9

#define BLOCKS_PER_B 32        // sims kernel: blocks per batch
#define RPG          4         // rows per warp group in sims kernel

// -------- scratch (no device allocation allowed -> __device__ globals) ------
__device__ float g_sims[BB * KC * NP];      // scaled cosine sims (1.3 MB)
__device__ float g_invnorm[BB * NP];        // 1/||patch||        (256 KB)

// ============================================================================
// Kernel 1: one pass over patches (268 MB streamed once -> memory bound).
// Cue is used RAW (un-normalized): per-(b,k) cue norm is a positive scalar
// on the whole sims row, so the top-9 set is unchanged, and the output only
// involves normalized patches. Each warp handles 4 rows at a time:
// 5 cue dots + self-dot per row, scalar FFMA, float4 loads.
// ============================================================================
__global__ void __launch_bounds__(256) sims_kernel(const float* __restrict__ patches,
                                                   const float* __restrict__ cue) {
    const int b = blockIdx.y;

    __shared__ float4 s_cue[KC * DD / 4];   // 5 x 1024 floats = 20 KB (raw cue)
    {
        const float4* src = (const float4*)(cue + (size_t)b * KC * DD);
        #pragma unroll
        for (int i = threadIdx.x; i < KC * DD / 4; i += 256) s_cue[i] = src[i];
    }
    __syncthreads();

    const int warp = threadIdx.x >> 5;
    const int lane = threadIdx.x & 31;
    const int rows_per_block = NP / BLOCKS_PER_B;          // 128
    const int row0 = blockIdx.x * rows_per_block;

    for (int g = warp * RPG; g < rows_per_block; g += 8 * RPG) {
        const int r = row0 + g;
        const float4* p =
            (const float4*)(patches + ((size_t)b * NP + r) * DD);

        float acc[RPG][6];
        #pragma unroll
        for (int rr = 0; rr < RPG; rr++)
            #pragma unroll
            for (int i = 0; i < 6; i++) acc[rr][i] = 0.f;

        #pragma unroll
        for (int j = 0; j < 8; j++) {
            const int off = lane + j * 32;                 // 256 float4 per row
            float4 v[RPG];
            #pragma unroll
            for (int rr = 0; rr < RPG; rr++) v[rr] = p[off + rr * (DD / 4)];

            #pragma unroll
            for (int rr = 0; rr < RPG; rr++) {
                acc[rr][5] = fmaf(v[rr].x, v[rr].x, acc[rr][5]);
                acc[rr][5] = fmaf(v[rr].y, v[rr].y, acc[rr][5]);
                acc[rr][5] = fmaf(v[rr].z, v[rr].z, acc[rr][5]);
                acc[rr][5] = fmaf(v[rr].w, v[rr].w, acc[rr][5]);
            }
            #pragma unroll
            for (int k = 0; k < KC; k++) {
                const float4 c = s_cue[k * (DD / 4) + off];
                #pragma unroll
                for (int rr = 0; rr < RPG; rr++) {
                    acc[rr][k] = fmaf(v[rr].x, c.x, acc[rr][k]);
                    acc[rr][k] = fmaf(v[rr].y, c.y, acc[rr][k]);
                    acc[rr][k] = fmaf(v[rr].z, c.z, acc[rr][k]);
                    acc[rr][k] = fmaf(v[rr].w, c.w, acc[rr][k]);
                }
            }
        }

        #pragma unroll
        for (int rr = 0; rr < RPG; rr++) {
            #pragma unroll
            for (int i = 0; i < 6; i++)
                #pragma unroll
                for (int o = 16; o; o >>= 1)
                    acc[rr][i] += __shfl_xor_sync(0xffffffffu, acc[rr][i], o);
            if (lane == 0) {
                const float inv = 1.0f / fmaxf(sqrtf(acc[rr][5]), 1e-12f);
                g_invnorm[(size_t)b * NP + r + rr] = inv;
                #pragma unroll
                for (int k = 0; k < KC; k++)
                    g_sims[((size_t)b * KC + k) * NP + r + rr] = acc[rr][k] * inv;
            }
        }
    }
}

// ============================================================================
// Kernel 2: per (b,k): top-9 over N=4096 sims (9 block-argmax passes over
// smem, lowest-index tie-break == jax.lax.top_k), then mean of the 9
// normalized patch rows. grid = 80 blocks, 256 threads.
// ============================================================================
__global__ void __launch_bounds__(256) topk_kernel(const float* __restrict__ patches,
                                                   float* __restrict__ out) {
    const int bk = blockIdx.x;          // 0..79
    const int b = bk / KC;

    __shared__ float s_sims[NP];        // 16 KB
    __shared__ float s_rv[8];
    __shared__ int   s_ri[8];
    __shared__ int   s_top[KNN];
    __shared__ float s_inv[KNN];

    {
        const float4* src = (const float4*)(g_sims + (size_t)bk * NP);
        float4* dst = (float4*)s_sims;
        #pragma unroll
        for (int i = threadIdx.x; i < NP / 4; i += 256) dst[i] = src[i];
    }
    __syncthreads();

    const int warp = threadIdx.x >> 5, lane = threadIdx.x & 31;

    for (int it = 0; it < KNN; it++) {
        float bv = -CUDART_INF_F;
        int bi = NP;
        for (int i = threadIdx.x; i < NP; i += 256) {
            float v = s_sims[i];
            if (v > bv) { bv = v; bi = i; }     // ascending i keeps lowest index on tie
        }
        #pragma unroll
        for (int o = 16; o; o >>= 1) {
            float ov = __shfl_xor_sync(0xffffffffu, bv, o);
            int   oi = __shfl_xor_sync(0xffffffffu, bi, o);
            if (ov > bv || (ov == bv && oi < bi)) { bv = ov; bi = oi; }
        }
        if (lane == 0) { s_rv[warp] = bv; s_ri[warp] = bi; }
        __syncthreads();
        if (warp == 0) {
            bv = (lane < 8) ? s_rv[lane] : -CUDART_INF_F;
            bi = (lane < 8) ? s_ri[lane] : NP;
            #pragma unroll
            for (int o = 4; o; o >>= 1) {
                float ov = __shfl_xor_sync(0xffffffffu, bv, o);
                int   oi = __shfl_xor_sync(0xffffffffu, bi, o);
                if (ov > bv || (ov == bv && oi < bi)) { bv = ov; bi = oi; }
            }
            if (lane == 0) {
                s_top[it] = bi;
                s_sims[bi] = -CUDART_INF_F;     // mask for next iteration
            }
        }
        __syncthreads();
    }

    if (threadIdx.x < KNN)
        s_inv[threadIdx.x] = g_invnorm[(size_t)b * NP + s_top[threadIdx.x]];
    __syncthreads();

    // each thread owns one float4 of the D=1024 output
    float4 acc = make_float4(0.f, 0.f, 0.f, 0.f);
    #pragma unroll
    for (int i = 0; i < KNN; i++) {
        const float4* prow =
            (const float4*)(patches + ((size_t)b * NP + s_top[i]) * DD);
        const float4 v = prow[threadIdx.x];
        const float inv = s_inv[i];
        acc.x += v.x * inv;
        acc.y += v.y * inv;
        acc.z += v.z * inv;
        acc.w += v.w * inv;
    }
    const float sc = 1.0f / (float)KNN;
    float4 o4 = make_float4(acc.x * sc, acc.y * sc, acc.z * sc, acc.w * sc);
    ((float4*)out)[(size_t)bk * (DD / 4) + threadIdx.x] = o4;
}

// ============================================================================
extern "C" void kernel_launch(void* const* d_in, const int* in_sizes, int n_in,
                              void* d_out, int out_size) {
    const float* cue     = (const float*)d_in[0];
    const float* patches = (const float*)d_in[1];
    // defensive: identify by element count (cue = 81920, patches = 67108864)
    if (n_in >= 2 && in_sizes[0] > in_sizes[1]) {
        cue     = (const float*)d_in[1];
        patches = (const float*)d_in[0];
    }

    dim3 g1(BLOCKS_PER_B, BB);
    sims_kernel<<<g1, 256>>>(patches, cue);

    topk_kernel<<<BB * KC, 256>>>(patches, (float*)d_out);
}